// round 3
// baseline (speedup 1.0000x reference)
#include <cuda_runtime.h>
#include <cuda_bf16.h>
#include <cstdint>

// Problem shapes (fixed for this dataset entry)
constexpr int B = 4;
constexpr int S = 4096;
constexpr int D = 2048;

constexpr int TT   = 64;   // t-tile per block
constexpr int HALO = 8;    // recurrence depth N_BLANKS
constexpr int LEAD = 4;    // load prefetch distance (iterations)
constexpr int DSPLIT  = 2;             // D halves per tile
constexpr int THREADS = D / 4 / DSPLIT;  // 256 threads, one float4 lane each

__global__ __launch_bounds__(THREADS)
void blank_embedding_kernel(const int* __restrict__ x,
                            const float* __restrict__ emb,
                            float* __restrict__ out)
{
    const int b   = blockIdx.y;
    const int T0  = blockIdx.x * TT;
    const int tid = threadIdx.x;
    const int d4  = tid + blockIdx.z * THREADS;   // float4 index within D-row

    // sidx[i] = BYTE offset of embedding row for t = T0 - HALO + i
    __shared__ int      sidx[TT + HALO + LEAD];
    // sp[i] = p[t] for t = T0 - 2*HALO + i
    __shared__ float    sp[TT + 2 * HALO];
    // weight DP buffers: wbuf[lvl&1][pos][j-1], pos owns t = T0 - HALO + pos
    __shared__ float    wbuf[2][TT + HALO][HALO];
    // per-output nonzero-weight bitmask (bits 1..8); 0 => fast path
    __shared__ unsigned sflag[TT];

    // ---- stage gather byte-offsets (clamped; weights guarantee halo terms are 0) ----
    for (int i = tid; i < TT + HALO + LEAD; i += THREADS) {
        int t = T0 - HALO + i;
        t = max(0, min(t, S - 1));
        sidx[i] = x[b * S + t] * (D * (int)sizeof(float));
    }
    // ---- stage p[t] = (x[t+1] < 16) && (x[t] >= 16), zero outside [0, S-1) ----
    for (int i = tid; i < TT + 2 * HALO; i += THREADS) {
        int t = T0 - 2 * HALO + i;
        float pv = 0.0f;
        if (t >= 0 && t + 1 < S) {
            int xt  = x[b * S + t];
            int xt1 = x[b * S + t + 1];
            pv = (xt1 < 16 && xt >= 16) ? 1.0f : 0.0f;
        }
        sp[i] = pv;
    }
    __syncthreads();

    // ---- cooperative weight DP: w^k[t][j] = w^{k-1}[t][j] + p[t-k] * w^{k-1}[t-1][j-1]
    //      (w_0 is identically 1 and kept implicit)                              ----
    float wloc[HALO];
#pragma unroll
    for (int j = 0; j < HALO; j++) wloc[j] = 0.0f;

    if (tid < TT + HALO) {
#pragma unroll
        for (int j = 0; j < HALO; j++) wbuf[0][tid][j] = 0.0f;
    }
    __syncthreads();

    for (int k = 1; k <= HALO; k++) {
        const int cur = k & 1, prv = cur ^ 1;
        if (tid < TT + HALO) {
            float nb[HALO];      // neighbor's previous-level w_j (w0 implicit)
            float nb0 = 0.0f;
            if (tid > 0) {
                nb0 = 1.0f;
#pragma unroll
                for (int j = 0; j < HALO - 1; j++) nb[j] = wbuf[prv][tid - 1][j];
            } else {
#pragma unroll
                for (int j = 0; j < HALO - 1; j++) nb[j] = 0.0f;
            }
            const float pv = sp[tid + HALO - k];
            wloc[0] = fmaf(pv, nb0, wloc[0]);
#pragma unroll
            for (int j = 1; j < HALO; j++) wloc[j] = fmaf(pv, nb[j - 1], wloc[j]);
#pragma unroll
            for (int j = 0; j < HALO; j++) wbuf[cur][tid][j] = wloc[j];
        }
        __syncthreads();
    }
    // final level k=8 -> buffer index 0
    if (tid >= HALO && tid < TT + HALO) {
        unsigned m = 0;
#pragma unroll
        for (int j = 0; j < HALO; j++)
            if (wbuf[0][tid][j] != 0.0f) m |= (1u << (j + 1));
        sflag[tid - HALO] = m;
    }
    __syncthreads();

    // ---- main streaming loop: out[t] = e[t] + sum_j w_j * e[t-j] ----
    const char* embp = (const char*)emb + (size_t)d4 * 16;
    float*      outp = out + ((size_t)(b * S + T0)) * D + (size_t)d4 * 4;

    float4 pipe[LEAD];
#pragma unroll
    for (int u = 0; u < LEAD; u++)
        pipe[u] = *reinterpret_cast<const float4*>(embp + sidx[HALO + u]);

    for (int g = 0; g < TT / LEAD; g++) {
#pragma unroll
        for (int u = 0; u < LEAD; u++) {
            const int i = g * LEAD + u;
            float4 c = pipe[u];
            // issue prefetch for i+LEAD immediately (sidx padded, always safe)
            pipe[u] = *reinterpret_cast<const float4*>(embp + sidx[HALO + i + LEAD]);

            const unsigned m = sflag[i];
            if (m) {
#pragma unroll
                for (int j = 1; j <= HALO; j++) {
                    if (m & (1u << j)) {
                        const float w = wbuf[0][i + HALO][j - 1];
                        const float4 h = *reinterpret_cast<const float4*>(
                            embp + sidx[HALO + i - j]);
                        c.x = fmaf(h.x, w, c.x);
                        c.y = fmaf(h.y, w, c.y);
                        c.z = fmaf(h.z, w, c.z);
                        c.w = fmaf(h.w, w, c.w);
                    }
                }
            }
            *reinterpret_cast<float4*>(outp + (size_t)i * D) = c;
        }
    }
}

extern "C" void kernel_launch(void* const* d_in, const int* in_sizes, int n_in,
                              void* d_out, int out_size)
{
    const int*   x   = (const int*)d_in[0];
    const float* emb = (const float*)d_in[1];
    float*       out = (float*)d_out;

    dim3 grid(S / TT, B, DSPLIT);   // 64 x 4 x 2 = 512 blocks of 256 threads
    blank_embedding_kernel<<<grid, THREADS>>>(x, emb, out);
}

// round 4
// speedup vs baseline: 1.0465x; 1.0465x over previous
#include <cuda_runtime.h>
#include <cuda_bf16.h>
#include <cstdint>

// Problem shapes (fixed for this dataset entry)
constexpr int B = 4;
constexpr int S = 4096;
constexpr int D = 2048;

constexpr int TT   = 64;   // t-tile per block
constexpr int HALO = 8;    // recurrence depth N_BLANKS
constexpr int LEAD = 4;    // load prefetch distance (iterations)
constexpr int DSPLIT = 4;                 // D quarters per tile
constexpr int TB     = D / 4 / DSPLIT;    // 128 threads, one float4 lane each

// Global scratch: per-(b,t) weights w_j (j=1..8) and nonzero-bit mask.
__device__ float    g_w[B * S * HALO];
__device__ unsigned g_flag[B * S];

// ---------------------------------------------------------------------------
// Kernel A: cooperative weight DP per t-tile.
//   w^k[t][j] = w^{k-1}[t][j] + p[t-k] * w^{k-1}[t-1][j-1],  w_0 == 1 implicit
//   p[t] = (x[t] >= 16) && (x[t+1] < 16), zero outside [0, S-1)
// ---------------------------------------------------------------------------
__global__ __launch_bounds__(128)
void weights_kernel(const int* __restrict__ x)
{
    const int b   = blockIdx.y;
    const int T0  = blockIdx.x * TT;
    const int tid = threadIdx.x;

    __shared__ float sp[TT + 2 * HALO];              // p[t], t = T0-2*HALO+i
    __shared__ float wbuf[2][TT + HALO][HALO];

    for (int i = tid; i < TT + 2 * HALO; i += 128) {
        int t = T0 - 2 * HALO + i;
        float pv = 0.0f;
        if (t >= 0 && t + 1 < S) {
            int xt  = x[b * S + t];
            int xt1 = x[b * S + t + 1];
            pv = (xt1 < 16 && xt >= 16) ? 1.0f : 0.0f;
        }
        sp[i] = pv;
    }
    float wloc[HALO];
#pragma unroll
    for (int j = 0; j < HALO; j++) wloc[j] = 0.0f;
    if (tid < TT + HALO) {
#pragma unroll
        for (int j = 0; j < HALO; j++) wbuf[0][tid][j] = 0.0f;
    }
    __syncthreads();

    for (int k = 1; k <= HALO; k++) {
        const int cur = k & 1, prv = cur ^ 1;
        if (tid < TT + HALO) {
            float nb[HALO - 1];
            float nb0 = 0.0f;
            if (tid > 0) {
                nb0 = 1.0f;
#pragma unroll
                for (int j = 0; j < HALO - 1; j++) nb[j] = wbuf[prv][tid - 1][j];
            } else {
#pragma unroll
                for (int j = 0; j < HALO - 1; j++) nb[j] = 0.0f;
            }
            const float pv = sp[tid + HALO - k];
            wloc[0] = fmaf(pv, nb0, wloc[0]);
#pragma unroll
            for (int j = 1; j < HALO; j++) wloc[j] = fmaf(pv, nb[j - 1], wloc[j]);
#pragma unroll
            for (int j = 0; j < HALO; j++) wbuf[cur][tid][j] = wloc[j];
        }
        __syncthreads();
    }

    if (tid >= HALO && tid < TT + HALO) {
        const int t = T0 - HALO + tid;               // in [T0, T0+TT)
        unsigned m = 0;
#pragma unroll
        for (int j = 0; j < HALO; j++) {
            if (wloc[j] != 0.0f) m |= (1u << (j + 1));
            g_w[((size_t)(b * S + t)) * HALO + j] = wloc[j];
        }
        g_flag[b * S + t] = m;
    }
}

// ---------------------------------------------------------------------------
// Kernel B: streaming gather  out[t] = e[t] + sum_j w_j(t) * e[t-j]
// ---------------------------------------------------------------------------
__global__ __launch_bounds__(TB, 10)
void main_kernel(const int* __restrict__ x,
                 const float* __restrict__ emb,
                 float* __restrict__ out)
{
    const int b   = blockIdx.y;
    const int T0  = blockIdx.x * TT;
    const int tid = threadIdx.x;
    const int d4  = tid + blockIdx.z * TB;           // float4 index within D

    __shared__ int      sidx[TT + HALO + LEAD];      // byte offsets of emb rows
    __shared__ unsigned sflag[TT];

    // stage gather byte-offsets for t = T0-HALO+i (clamped; zero-weight halo)
    if (tid < TT + HALO + LEAD) {
        int t = T0 - HALO + tid;
        t = max(0, min(t, S - 1));
        sidx[tid] = x[b * S + t] * (D * (int)sizeof(float));
    }
    if (tid < TT) sflag[tid] = g_flag[b * S + T0 + tid];
    __syncthreads();

    const char* embp = (const char*)emb + (size_t)d4 * 16;
    float*      outp = out + ((size_t)(b * S + T0)) * D + (size_t)d4 * 4;
    const float* wrow = g_w + ((size_t)(b * S + T0)) * HALO;

    float4 pipe[LEAD];
#pragma unroll
    for (int u = 0; u < LEAD; u++)
        pipe[u] = *reinterpret_cast<const float4*>(embp + sidx[HALO + u]);

    for (int g = 0; g < TT / LEAD; g++) {
#pragma unroll
        for (int u = 0; u < LEAD; u++) {
            const int i = g * LEAD + u;
            float4 c = pipe[u];
            pipe[u] = *reinterpret_cast<const float4*>(embp + sidx[HALO + i + LEAD]);

            const unsigned m = sflag[i];
            if (m) {
#pragma unroll
                for (int j = 1; j <= HALO; j++) {
                    if (m & (1u << j)) {
                        const float w = __ldg(wrow + (size_t)i * HALO + (j - 1));
                        const float4 h = *reinterpret_cast<const float4*>(
                            embp + sidx[HALO + i - j]);
                        c.x = fmaf(h.x, w, c.x);
                        c.y = fmaf(h.y, w, c.y);
                        c.z = fmaf(h.z, w, c.z);
                        c.w = fmaf(h.w, w, c.w);
                    }
                }
            }
            *reinterpret_cast<float4*>(outp + (size_t)i * D) = c;
        }
    }
}

extern "C" void kernel_launch(void* const* d_in, const int* in_sizes, int n_in,
                              void* d_out, int out_size)
{
    const int*   x   = (const int*)d_in[0];
    const float* emb = (const float*)d_in[1];
    float*       out = (float*)d_out;

    dim3 gridA(S / TT, B);            // 64 x 4 = 256 blocks
    weights_kernel<<<gridA, 128>>>(x);

    dim3 gridB(S / TT, B, DSPLIT);    // 64 x 4 x 4 = 1024 blocks of 128
    main_kernel<<<gridB, TB>>>(x, emb, out);
}

// round 5
// speedup vs baseline: 1.1376x; 1.0871x over previous
#include <cuda_runtime.h>
#include <cuda_bf16.h>
#include <cstdint>

// Problem shapes (fixed for this dataset entry)
constexpr int B = 4;
constexpr int S = 4096;
constexpr int D = 2048;

constexpr int HALO = 8;    // recurrence depth N_BLANKS
constexpr int LEAD = 4;    // load prefetch distance (iterations)

// weights kernel tiling
constexpr int TTW = 64;

// main kernel tiling
constexpr int TTM    = 32;                // t-tile per block
constexpr int DSPLIT = 4;                 // D quarters per tile
constexpr int TB     = D / 4 / DSPLIT;    // 128 threads, one float4 lane each

// Global scratch: per-(b,t) weights w_j (j=1..8) and nonzero-bit mask.
__device__ float    g_w[B * S * HALO];
__device__ unsigned g_flag[B * S];

// ---------------------------------------------------------------------------
// Kernel A: cooperative weight DP per t-tile.
//   w^k[t][j] = w^{k-1}[t][j] + p[t-k] * w^{k-1}[t-1][j-1],  w_0 == 1 implicit
//   p[t] = (x[t] >= 16) && (x[t+1] < 16), zero outside [0, S-1)
// ---------------------------------------------------------------------------
__global__ __launch_bounds__(128)
void weights_kernel(const int* __restrict__ x)
{
    const int b   = blockIdx.y;
    const int T0  = blockIdx.x * TTW;
    const int tid = threadIdx.x;

    __shared__ float sp[TTW + 2 * HALO];             // p[t], t = T0-2*HALO+i
    __shared__ float wbuf[2][TTW + HALO][HALO];

    for (int i = tid; i < TTW + 2 * HALO; i += 128) {
        int t = T0 - 2 * HALO + i;
        float pv = 0.0f;
        if (t >= 0 && t + 1 < S) {
            int xt  = x[b * S + t];
            int xt1 = x[b * S + t + 1];
            pv = (xt1 < 16 && xt >= 16) ? 1.0f : 0.0f;
        }
        sp[i] = pv;
    }
    float wloc[HALO];
#pragma unroll
    for (int j = 0; j < HALO; j++) wloc[j] = 0.0f;
    if (tid < TTW + HALO) {
#pragma unroll
        for (int j = 0; j < HALO; j++) wbuf[0][tid][j] = 0.0f;
    }
    __syncthreads();

    for (int k = 1; k <= HALO; k++) {
        const int cur = k & 1, prv = cur ^ 1;
        if (tid < TTW + HALO) {
            float nb[HALO - 1];
            float nb0 = 0.0f;
            if (tid > 0) {
                nb0 = 1.0f;
#pragma unroll
                for (int j = 0; j < HALO - 1; j++) nb[j] = wbuf[prv][tid - 1][j];
            } else {
#pragma unroll
                for (int j = 0; j < HALO - 1; j++) nb[j] = 0.0f;
            }
            const float pv = sp[tid + HALO - k];
            wloc[0] = fmaf(pv, nb0, wloc[0]);
#pragma unroll
            for (int j = 1; j < HALO; j++) wloc[j] = fmaf(pv, nb[j - 1], wloc[j]);
#pragma unroll
            for (int j = 0; j < HALO; j++) wbuf[cur][tid][j] = wloc[j];
        }
        __syncthreads();
    }

    if (tid >= HALO && tid < TTW + HALO) {
        const int t = T0 - HALO + tid;               // in [T0, T0+TTW)
        unsigned m = 0;
#pragma unroll
        for (int j = 0; j < HALO; j++) {
            if (wloc[j] != 0.0f) m |= (1u << (j + 1));
            g_w[((size_t)(b * S + t)) * HALO + j] = wloc[j];
        }
        g_flag[b * S + t] = m;
    }
}

// ---------------------------------------------------------------------------
// Kernel B: streaming gather  out[t] = e[t] + sum_j w_j(t) * e[t-j]
// ---------------------------------------------------------------------------
__global__ __launch_bounds__(TB, 10)
void main_kernel(const int* __restrict__ x,
                 const float* __restrict__ emb,
                 float* __restrict__ out)
{
    const int b   = blockIdx.y;
    const int T0  = blockIdx.x * TTM;
    const int tid = threadIdx.x;
    const int d4  = tid + blockIdx.z * TB;           // float4 index within D

    __shared__ int      sidx[TTM + HALO + LEAD];     // byte offsets of emb rows
    __shared__ unsigned sflag[TTM];

    // stage gather byte-offsets for t = T0-HALO+i (clamped; zero-weight halo)
    if (tid < TTM + HALO + LEAD) {
        int t = T0 - HALO + tid;
        t = max(0, min(t, S - 1));
        sidx[tid] = x[b * S + t] * (D * (int)sizeof(float));
    }
    if (tid < TTM) sflag[tid] = g_flag[b * S + T0 + tid];
    __syncthreads();

    const char* embp = (const char*)emb + (size_t)d4 * 16;
    float*      outp = out + ((size_t)(b * S + T0)) * D + (size_t)d4 * 4;
    const float* wrow = g_w + ((size_t)(b * S + T0)) * HALO;

    float4 pipe[LEAD];
#pragma unroll
    for (int u = 0; u < LEAD; u++)
        pipe[u] = *reinterpret_cast<const float4*>(embp + sidx[HALO + u]);

    for (int g = 0; g < TTM / LEAD; g++) {
#pragma unroll
        for (int u = 0; u < LEAD; u++) {
            const int i = g * LEAD + u;
            float4 c = pipe[u];
            pipe[u] = *reinterpret_cast<const float4*>(embp + sidx[HALO + i + LEAD]);

            const unsigned m = sflag[i];
            if (m) {
#pragma unroll
                for (int j = 1; j <= HALO; j++) {
                    if (m & (1u << j)) {
                        const float w = __ldg(wrow + (size_t)i * HALO + (j - 1));
                        const float4 h = *reinterpret_cast<const float4*>(
                            embp + sidx[HALO + i - j]);
                        c.x = fmaf(h.x, w, c.x);
                        c.y = fmaf(h.y, w, c.y);
                        c.z = fmaf(h.z, w, c.z);
                        c.w = fmaf(h.w, w, c.w);
                    }
                }
            }
            // streaming store: evict-first, keep emb table resident in L2
            __stcs(reinterpret_cast<float4*>(outp + (size_t)i * D), c);
        }
    }
}

extern "C" void kernel_launch(void* const* d_in, const int* in_sizes, int n_in,
                              void* d_out, int out_size)
{
    const int*   x   = (const int*)d_in[0];
    const float* emb = (const float*)d_in[1];
    float*       out = (float*)d_out;

    dim3 gridA(S / TTW, B);           // 64 x 4 = 256 blocks
    weights_kernel<<<gridA, 128>>>(x);

    dim3 gridB(S / TTM, B, DSPLIT);   // 128 x 4 x 4 = 2048 blocks of 128
    main_kernel<<<gridB, TB>>>(x, emb, out);
}

// round 6
// speedup vs baseline: 1.2578x; 1.1056x over previous
#include <cuda_runtime.h>
#include <cuda_bf16.h>
#include <cstdint>

// Problem shapes (fixed for this dataset entry)
constexpr int B = 4;
constexpr int S = 4096;
constexpr int D = 2048;

constexpr int HALO = 8;    // recurrence depth N_BLANKS
constexpr int LEAD = 4;    // load prefetch distance (iterations)

constexpr int TTM    = 32;                // t-tile per block
constexpr int DSPLIT = 4;                 // D quarters per tile
constexpr int TB     = D / 4 / DSPLIT;    // 128 threads, one float4 lane each

// ---------------------------------------------------------------------------
// Fused kernel.
//  Warps 0-1: warp-shuffle weight DP
//     w^k[t][j] = w^{k-1}[t][j] + p[t-k] * w^{k-1}[t-1][j-1],  w_0 == 1 implicit
//     p[t] = (x[t] >= 16) && (x[t+1] < 16), zero outside [0, S-1)
//     lane = t position; neighbor via shfl_up; influence moves 1 lane per level,
//     so lanes >= 8 hold exact weights (8-lane halo discarded).
//     warp0 covers t in [T0-8, T0+24) -> outputs i = 0..23
//     warp1 covers t in [T0+16, T0+48) -> outputs i = 24..31 (rest dropped)
//  Warps 2-3: stage gather byte-offsets.
//  Then all warps stream: out[t] = e[t] + sum_j w_j(t) * e[t-j]
// ---------------------------------------------------------------------------
__global__ __launch_bounds__(TB, 10)
void fused_kernel(const int* __restrict__ x,
                  const float* __restrict__ emb,
                  float* __restrict__ out)
{
    const int b    = blockIdx.y;
    const int T0   = blockIdx.x * TTM;
    const int tid  = threadIdx.x;
    const int wid  = tid >> 5;
    const int lane = tid & 31;
    const int d4   = tid + blockIdx.z * TB;          // float4 index within D

    __shared__ int      sidx[TTM + HALO + LEAD];     // byte offsets of emb rows
    __shared__ float    sw[TTM][HALO];               // weights w_1..w_8 per t
    __shared__ unsigned sflag[TTM];

    if (wid >= 2) {
        // ---- stage gather byte-offsets for t = T0-HALO+i (clamped; halo weights are 0)
        const int i = tid - 64;
        if (i < TTM + HALO + LEAD) {
            int t = T0 - HALO + i;
            t = max(0, min(t, S - 1));
            sidx[i] = x[b * S + t] * (D * (int)sizeof(float));
        }
    } else {
        // ---- warp-shuffle weight DP ----
        const int base = (wid == 0) ? (T0 - HALO) : (T0 + 2 * HALO);
        const int t    = base + lane;

        // xs[i] = x[t-8+i], i = 0..8 (clamped loads; predicates kill OOB)
        int xs[9];
#pragma unroll
        for (int i = 0; i < 9; i++) {
            int s = t - 8 + i;
            s = max(0, min(s, S - 1));
            xs[i] = x[b * S + s];
        }
        // pmask bit k (k=1..8): p[t-k] != 0
        unsigned pm = 0;
#pragma unroll
        for (int k = 1; k <= 8; k++) {
            int s = t - k;
            if (s >= 0 && s + 1 < S && xs[8 - k] >= 16 && xs[9 - k] < 16)
                pm |= (1u << k);
        }

        float wj[HALO];
#pragma unroll
        for (int j = 0; j < HALO; j++) wj[j] = 0.0f;

#pragma unroll
        for (int k = 1; k <= 8; k++) {
            const float pv = (pm >> k) & 1u ? 1.0f : 0.0f;
            float nb[HALO - 1];
#pragma unroll
            for (int j = 0; j < HALO - 1; j++)
                nb[j] = __shfl_up_sync(0xFFFFFFFFu, wj[j], 1);
            float nb0 = 1.0f;
            if (lane == 0) {
                nb0 = 0.0f;
#pragma unroll
                for (int j = 0; j < HALO - 1; j++) nb[j] = 0.0f;
            }
            wj[0] = fmaf(pv, nb0, wj[0]);
#pragma unroll
            for (int j = 1; j < HALO; j++) wj[j] = fmaf(pv, nb[j - 1], wj[j]);
        }

        const int i = t - T0;
        if (lane >= HALO && i >= 0 && i < TTM) {
            unsigned m = 0;
#pragma unroll
            for (int j = 0; j < HALO; j++) {
                sw[i][j] = wj[j];
                if (wj[j] != 0.0f) m |= (1u << (j + 1));
            }
            sflag[i] = m;
        }
    }
    __syncthreads();

    // ---- main streaming loop: out[t] = e[t] + sum_j w_j(t) * e[t-j] ----
    const char* embp = (const char*)emb + (size_t)d4 * 16;
    float*      outp = out + ((size_t)(b * S + T0)) * D + (size_t)d4 * 4;

    float4 pipe[LEAD];
#pragma unroll
    for (int u = 0; u < LEAD; u++)
        pipe[u] = *reinterpret_cast<const float4*>(embp + sidx[HALO + u]);

    for (int g = 0; g < TTM / LEAD; g++) {
#pragma unroll
        for (int u = 0; u < LEAD; u++) {
            const int i = g * LEAD + u;
            float4 c = pipe[u];
            pipe[u] = *reinterpret_cast<const float4*>(embp + sidx[HALO + i + LEAD]);

            const unsigned m = sflag[i];
            if (m) {
#pragma unroll
                for (int j = 1; j <= HALO; j++) {
                    if (m & (1u << j)) {
                        const float w = sw[i][j - 1];
                        const float4 h = *reinterpret_cast<const float4*>(
                            embp + sidx[HALO + i - j]);
                        c.x = fmaf(h.x, w, c.x);
                        c.y = fmaf(h.y, w, c.y);
                        c.z = fmaf(h.z, w, c.z);
                        c.w = fmaf(h.w, w, c.w);
                    }
                }
            }
            // streaming store: evict-first, keep emb table resident in L2
            __stcs(reinterpret_cast<float4*>(outp + (size_t)i * D), c);
        }
    }
}

extern "C" void kernel_launch(void* const* d_in, const int* in_sizes, int n_in,
                              void* d_out, int out_size)
{
    const int*   x   = (const int*)d_in[0];
    const float* emb = (const float*)d_in[1];
    float*       out = (float*)d_out;

    dim3 grid(S / TTM, B, DSPLIT);   // 128 x 4 x 4 = 2048 blocks of 128
    fused_kernel<<<grid, TB>>>(x, emb, out);
}